// round 1
// baseline (speedup 1.0000x reference)
#include <cuda_runtime.h>
#include <cuda_bf16.h>

#define DH 256
#define NMAX 50000
#define EMAX 800000
#define GNUM 64
#define BN_EPS 1e-5f

// ---------------- scratch (static device memory; no runtime allocation) ----------------
__device__ float g_H [NMAX * DH];
__device__ float g_A [NMAX * DH];
__device__ float g_T1[NMAX * DH];
__device__ float g_T2[NMAX * DH];
__device__ int   g_deg[NMAX + 1];
__device__ int   g_rowptr[NMAX + 1];
__device__ int   g_cursor[NMAX];
__device__ int   g_eidx[EMAX];
__device__ float g_part[256 * 512];     // per-block column partials: [block][sum(256), sumsq(256)]
__device__ float g_ac[3 * 512];         // folded BN (a,c) for bn1 / bnA / bnG
__device__ int   g_gstart[GNUM + 1];
__device__ float g_R[2 * GNUM * DH];

// ---------------- small utility kernels ----------------
__global__ __launch_bounds__(256) void zero_int_k(int* p, int n) {
    int i = blockIdx.x * 256 + threadIdx.x;
    if (i < n) p[i] = 0;
}

__global__ __launch_bounds__(256) void hist_k(const int* __restrict__ dst, int ne, int* deg) {
    int i = blockIdx.x * 256 + threadIdx.x;
    if (i < ne) atomicAdd(&deg[dst[i]], 1);
}

// single-block inclusive scan over deg -> rowptr (exclusive form: rowptr[0]=0, rowptr[i+1]=sum deg[0..i])
__global__ void scan_k(const int* __restrict__ deg, int* __restrict__ rowptr, int n) {
    __shared__ int sh[2][1024];
    int tid = threadIdx.x;
    int carry = 0;
    for (int base = 0; base < n; base += 1024) {
        int i = base + tid;
        int v = (i < n) ? deg[i] : 0;
        int buf = 0;
        sh[0][tid] = v;
        __syncthreads();
        for (int off = 1; off < 1024; off <<= 1) {
            int nb = buf ^ 1;
            int x = sh[buf][tid];
            if (tid >= off) x += sh[buf][tid - off];
            sh[nb][tid] = x;
            __syncthreads();
            buf = nb;
        }
        if (i < n) rowptr[i + 1] = carry + sh[buf][tid];
        carry += sh[buf][1023];
        __syncthreads();
    }
    if (tid == 0) rowptr[0] = 0;
}

__global__ __launch_bounds__(256) void copy_int_k(const int* __restrict__ a, int* __restrict__ b, int n) {
    int i = blockIdx.x * 256 + threadIdx.x;
    if (i < n) b[i] = a[i];
}

__global__ __launch_bounds__(256) void fill_k(const int* __restrict__ src, const int* __restrict__ dst,
                                              int ne, int* cursor, int* __restrict__ eidx) {
    int i = blockIdx.x * 256 + threadIdx.x;
    if (i < ne) {
        int p = atomicAdd(&cursor[dst[i]], 1);
        eidx[p] = src[i];
    }
}

// group boundaries in a sorted gid array (lower_bound per group)
__global__ void bounds_k(const int* __restrict__ gid, int n, int* __restrict__ gs) {
    int g = threadIdx.x;
    if (g > GNUM) return;
    int lo = 0, hi = n;
    while (lo < hi) {
        int mid = (lo + hi) >> 1;
        if (gid[mid] < g) lo = mid + 1; else hi = mid;
    }
    gs[g] = lo;
}

// ---------------- GIN aggregation: A[i] = (1+eps)*H[i] + sum_{src in CSR[i]} H[src] ----------------
__global__ void agg_k(const float* __restrict__ H, float* __restrict__ A,
                      const int* __restrict__ rowptr, const int* __restrict__ eidx,
                      const float* __restrict__ eps, int l, int n) {
    int node = blockIdx.x * 8 + threadIdx.y;
    if (node >= n) return;
    int lane = threadIdx.x;
    const float4* h4 = (const float4*)(H + (size_t)node * DH);
    float ep = 1.0f + eps[l];
    float4 a0 = h4[lane];
    float4 a1 = h4[lane + 32];
    a0.x *= ep; a0.y *= ep; a0.z *= ep; a0.w *= ep;
    a1.x *= ep; a1.y *= ep; a1.z *= ep; a1.w *= ep;
    int beg = rowptr[node], end = rowptr[node + 1];
    for (int j = beg; j < end; j++) {
        const float4* s4 = (const float4*)(H + (size_t)eidx[j] * DH);
        float4 b0 = s4[lane];
        float4 b1 = s4[lane + 32];
        a0.x += b0.x; a0.y += b0.y; a0.z += b0.z; a0.w += b0.w;
        a1.x += b1.x; a1.y += b1.y; a1.z += b1.z; a1.w += b1.w;
    }
    float4* o4 = (float4*)(A + (size_t)node * DH);
    o4[lane] = a0;
    o4[lane + 32] = a1;
}

// ---------------- fp32 tiled GEMM: C = op(A) @ B + bias ----------------
// TRANS=1 applies per-K-column transform relu(tac[k]*x + tac[256+k]) to A at load (folded BN+ReLU).
template <int TRANS>
__global__ __launch_bounds__(256) void gemm_k(
    const float* __restrict__ A, const float* __restrict__ B,
    const float* __restrict__ bias, const float* __restrict__ tac,
    float* __restrict__ C, int M, int K, int N)
{
    __shared__ float As[16][128];
    __shared__ float Bs[16][128];
    int t = threadIdx.x;
    int rbase = (t >> 4) * 4;
    int cbase = (t & 15) * 4;
    int m0 = blockIdx.x * 128;
    int n0 = blockIdx.y * 128;
    float acc[8][8];
#pragma unroll
    for (int i = 0; i < 8; i++)
#pragma unroll
        for (int j = 0; j < 8; j++) acc[i][j] = 0.0f;

    for (int k0 = 0; k0 < K; k0 += 16) {
#pragma unroll
        for (int u = 0; u < 2; u++) {
            int f = t + u * 256;
            int r = f >> 2, kq = (f & 3) * 4;
            float4 v = make_float4(0.f, 0.f, 0.f, 0.f);
            if (m0 + r < M) v = *(const float4*)&A[(size_t)(m0 + r) * K + k0 + kq];
            if (TRANS) {
                float4 av = *(const float4*)&tac[k0 + kq];
                float4 cv = *(const float4*)&tac[256 + k0 + kq];
                v.x = fmaxf(av.x * v.x + cv.x, 0.f);
                v.y = fmaxf(av.y * v.y + cv.y, 0.f);
                v.z = fmaxf(av.z * v.z + cv.z, 0.f);
                v.w = fmaxf(av.w * v.w + cv.w, 0.f);
            }
            As[kq + 0][r] = v.x;
            As[kq + 1][r] = v.y;
            As[kq + 2][r] = v.z;
            As[kq + 3][r] = v.w;
        }
#pragma unroll
        for (int u = 0; u < 2; u++) {
            int f = t + u * 256;
            int kr = f >> 5, c4 = (f & 31) * 4;
            *(float4*)&Bs[kr][c4] = *(const float4*)&B[(size_t)(k0 + kr) * N + n0 + c4];
        }
        __syncthreads();
#pragma unroll
        for (int kk = 0; kk < 16; kk++) {
            float4 ra0 = *(const float4*)&As[kk][rbase];
            float4 ra1 = *(const float4*)&As[kk][rbase + 64];
            float4 rb0 = *(const float4*)&Bs[kk][cbase];
            float4 rb1 = *(const float4*)&Bs[kk][cbase + 64];
            float ra[8] = {ra0.x, ra0.y, ra0.z, ra0.w, ra1.x, ra1.y, ra1.z, ra1.w};
            float rb[8] = {rb0.x, rb0.y, rb0.z, rb0.w, rb1.x, rb1.y, rb1.z, rb1.w};
#pragma unroll
            for (int i = 0; i < 8; i++)
#pragma unroll
                for (int j = 0; j < 8; j++) acc[i][j] += ra[i] * rb[j];
        }
        __syncthreads();
    }

    float4 bb0 = *(const float4*)&bias[n0 + cbase];
    float4 bb1 = *(const float4*)&bias[n0 + cbase + 64];
#pragma unroll
    for (int i = 0; i < 8; i++) {
        int r = m0 + ((i < 4) ? (rbase + i) : (rbase + i + 60));
        if (r >= M) continue;
        float4 o0 = make_float4(acc[i][0] + bb0.x, acc[i][1] + bb0.y,
                                acc[i][2] + bb0.z, acc[i][3] + bb0.w);
        float4 o1 = make_float4(acc[i][4] + bb1.x, acc[i][5] + bb1.y,
                                acc[i][6] + bb1.z, acc[i][7] + bb1.w);
        *(float4*)&C[(size_t)r * N + n0 + cbase] = o0;
        *(float4*)&C[(size_t)r * N + n0 + cbase + 64] = o1;
    }
}

// ---------------- column stats (two-stage, atomic-free) ----------------
// TRANS=1: stats of relu(tac[c]*x + tac[256+c]) instead of x.
template <int TRANS>
__global__ void colstats_k(const float* __restrict__ T, const float* __restrict__ tac,
                           float* __restrict__ part, int M) {
    int c = threadIdx.x;
    int r0 = blockIdx.x * 256;
    int r1 = min(r0 + 256, M);
    float a = 0.f, b = 0.f;
    if (TRANS) { a = tac[c]; b = tac[256 + c]; }
    float s = 0.f, ss = 0.f;
    for (int r = r0; r < r1; r++) {
        float x = T[(size_t)r * DH + c];
        if (TRANS) x = fmaxf(a * x + b, 0.f);
        s += x;
        ss += x * x;
    }
    part[blockIdx.x * 512 + c] = s;
    part[blockIdx.x * 512 + 256 + c] = ss;
}

__global__ void finalize_k(const float* __restrict__ part, int nb, int n,
                           const float* __restrict__ gamma, const float* __restrict__ beta,
                           float* __restrict__ ac) {
    int c = threadIdx.x;
    float s = 0.f, ss = 0.f;
    for (int b = 0; b < nb; b++) {
        s += part[b * 512 + c];
        ss += part[b * 512 + 256 + c];
    }
    float inv = 1.0f / (float)n;
    float m = s * inv;
    float v = ss * inv - m * m;
    float a = gamma[c] * rsqrtf(v + BN_EPS);
    ac[c] = a;
    ac[256 + c] = beta[c] - a * m;
}

// H += relu(aG * relu(aA * T2 + cA) + cG)
__global__ __launch_bounds__(256) void update_k(float* __restrict__ H, const float* __restrict__ T2,
                                                const float* __restrict__ acA, const float* __restrict__ acG,
                                                int n4) {
    int i = blockIdx.x * 256 + threadIdx.x;
    if (i >= n4) return;
    int cb = (i * 4) & 255;
    float4 t  = ((const float4*)T2)[i];
    float4 aA = *(const float4*)&acA[cb];
    float4 cA = *(const float4*)&acA[256 + cb];
    float4 aG = *(const float4*)&acG[cb];
    float4 cG = *(const float4*)&acG[256 + cb];
    float4 h  = ((float4*)H)[i];
    h.x += fmaxf(aG.x * fmaxf(aA.x * t.x + cA.x, 0.f) + cG.x, 0.f);
    h.y += fmaxf(aG.y * fmaxf(aA.y * t.y + cA.y, 0.f) + cG.y, 0.f);
    h.z += fmaxf(aG.z * fmaxf(aA.z * t.z + cA.z, 0.f) + cG.z, 0.f);
    h.w += fmaxf(aG.w * fmaxf(aA.w * t.w + cA.w, 0.f) + cG.w, 0.f);
    ((float4*)H)[i] = h;
}

// sum-readout per graph (gid is sorted -> contiguous ranges)
__global__ void readout_k(const float* __restrict__ H, const int* __restrict__ gs,
                          float* __restrict__ R) {
    int g = blockIdx.x;
    int c = threadIdx.x;
    int beg = gs[g], end = gs[g + 1];
    float s = 0.f;
    for (int i = beg; i < end; i++) s += H[(size_t)i * DH + c];
    R[g * DH + c] = s;
}

// y[g] = relu(|Rg-Rq| @ Wp1 + bp1) @ Wp2 + bp2
__global__ void predict_k(const float* __restrict__ Rg, const float* __restrict__ Rq,
                          const float* __restrict__ Wp1, const float* __restrict__ bp1,
                          const float* __restrict__ Wp2, const float* __restrict__ bp2,
                          float* __restrict__ out) {
    int g = blockIdx.x;
    int t = threadIdx.x;
    __shared__ float d[256];
    __shared__ float red[256];
    d[t] = fabsf(Rg[g * DH + t] - Rq[g * DH + t]);
    __syncthreads();
    float acc = bp1[t];
    for (int k = 0; k < 256; k++) acc += d[k] * Wp1[k * 256 + t];
    acc = fmaxf(acc, 0.f);
    red[t] = acc * Wp2[t];
    __syncthreads();
    for (int s = 128; s > 0; s >>= 1) {
        if (t < s) red[t] += red[t + s];
        __syncthreads();
    }
    if (t == 0) out[g] = red[0] + bp2[0];
}

// ---------------- host orchestration ----------------
struct Scratch {
    float *H, *A, *T1, *T2, *part, *ac, *R;
    int *deg, *rowptr, *cursor, *eidx, *gstart;
};

static void get_scratch(Scratch& s) {
    cudaGetSymbolAddress((void**)&s.H, g_H);
    cudaGetSymbolAddress((void**)&s.A, g_A);
    cudaGetSymbolAddress((void**)&s.T1, g_T1);
    cudaGetSymbolAddress((void**)&s.T2, g_T2);
    cudaGetSymbolAddress((void**)&s.part, g_part);
    cudaGetSymbolAddress((void**)&s.ac, g_ac);
    cudaGetSymbolAddress((void**)&s.R, g_R);
    cudaGetSymbolAddress((void**)&s.deg, g_deg);
    cudaGetSymbolAddress((void**)&s.rowptr, g_rowptr);
    cudaGetSymbolAddress((void**)&s.cursor, g_cursor);
    cudaGetSymbolAddress((void**)&s.eidx, g_eidx);
    cudaGetSymbolAddress((void**)&s.gstart, g_gstart);
}

static void run_graph(const Scratch& sc, const float* X, int n,
                      const int* src, const int* dst, int ne, const int* gid,
                      const float* W_emb, const float* b_emb, const float* eps,
                      const float* W1, const float* b1,
                      const float* bn1_g, const float* bn1_b,
                      const float* W2, const float* b2,
                      const float* bnA_g, const float* bnA_b,
                      const float* bnG_g, const float* bnG_b,
                      float* R) {
    int gx = (n + 127) / 128;
    int sb = (n + 255) / 256;

    // node embedding: H = X @ W_emb + b_emb   (K=128)
    gemm_k<0><<<dim3(gx, 2), 256>>>(X, W_emb, b_emb, nullptr, sc.H, n, 128, 256);

    // CSR by destination
    zero_int_k<<<(n + 256) / 256, 256>>>(sc.deg, n + 1);
    hist_k<<<(ne + 255) / 256, 256>>>(dst, ne, sc.deg);
    scan_k<<<1, 1024>>>(sc.deg, sc.rowptr, n);
    copy_int_k<<<(n + 255) / 256, 256>>>(sc.rowptr, sc.cursor, n);
    fill_k<<<(ne + 255) / 256, 256>>>(src, dst, ne, sc.cursor, sc.eidx);
    bounds_k<<<1, GNUM + 1>>>(gid, n, sc.gstart);

    for (int l = 0; l < 4; l++) {
        size_t wo = (size_t)l * 256 * 256;
        int bo = l * 256;
        agg_k<<<(n + 7) / 8, dim3(32, 8)>>>(sc.H, sc.A, sc.rowptr, sc.eidx, eps, l, n);
        // T1 = A @ W1 + b1
        gemm_k<0><<<dim3(gx, 2), 256>>>(sc.A, W1 + wo, b1 + bo, nullptr, sc.T1, n, 256, 256);
        colstats_k<0><<<sb, 256>>>(sc.T1, nullptr, sc.part, n);
        finalize_k<<<1, 256>>>(sc.part, sb, n, bn1_g + bo, bn1_b + bo, sc.ac);           // bn1 fold
        // T2 = relu(bn1(T1)) @ W2 + b2   (bn1+relu fused into A-load)
        gemm_k<1><<<dim3(gx, 2), 256>>>(sc.T1, W2 + wo, b2 + bo, sc.ac, sc.T2, n, 256, 256);
        colstats_k<0><<<sb, 256>>>(sc.T2, nullptr, sc.part, n);
        finalize_k<<<1, 256>>>(sc.part, sb, n, bnA_g + bo, bnA_b + bo, sc.ac + 512);     // bnA fold
        colstats_k<1><<<sb, 256>>>(sc.T2, sc.ac + 512, sc.part, n);                      // stats of relu(bnA(T2))
        finalize_k<<<1, 256>>>(sc.part, sb, n, bnG_g + bo, bnG_b + bo, sc.ac + 1024);    // bnG fold
        update_k<<<((n * 64) + 255) / 256, 256>>>(sc.H, sc.T2, sc.ac + 512, sc.ac + 1024, n * 64);
    }
    readout_k<<<GNUM, 256>>>(sc.H, sc.gstart, R);
}

extern "C" void kernel_launch(void* const* d_in, const int* in_sizes, int n_in,
                              void* d_out, int out_size) {
    const float* X     = (const float*)d_in[0];
    const float* X_q   = (const float*)d_in[2];
    const float* W_emb = (const float*)d_in[4];
    const float* b_emb = (const float*)d_in[5];
    const float* eps   = (const float*)d_in[6];
    const float* W1    = (const float*)d_in[7];
    const float* b1    = (const float*)d_in[8];
    const float* bn1_g = (const float*)d_in[9];
    const float* bn1_b = (const float*)d_in[10];
    const float* W2    = (const float*)d_in[11];
    const float* b2    = (const float*)d_in[12];
    const float* bnA_g = (const float*)d_in[13];
    const float* bnA_b = (const float*)d_in[14];
    const float* bnG_g = (const float*)d_in[15];
    const float* bnG_b = (const float*)d_in[16];
    const float* Wp1   = (const float*)d_in[17];
    const float* bp1   = (const float*)d_in[18];
    const float* Wp2   = (const float*)d_in[19];
    const float* bp2   = (const float*)d_in[20];
    const int* src_g   = (const int*)d_in[21];
    const int* dst_g   = (const int*)d_in[22];
    const int* gid_g   = (const int*)d_in[23];
    const int* src_q   = (const int*)d_in[24];
    const int* dst_q   = (const int*)d_in[25];
    const int* gid_q   = (const int*)d_in[26];

    int n_g = in_sizes[0] / 128;
    int e_g = in_sizes[21];
    int n_q = in_sizes[2] / 128;
    int e_q = in_sizes[24];

    Scratch sc;
    get_scratch(sc);

    run_graph(sc, X, n_g, src_g, dst_g, e_g, gid_g, W_emb, b_emb, eps,
              W1, b1, bn1_g, bn1_b, W2, b2, bnA_g, bnA_b, bnG_g, bnG_b,
              sc.R);
    run_graph(sc, X_q, n_q, src_q, dst_q, e_q, gid_q, W_emb, b_emb, eps,
              W1, b1, bn1_g, bn1_b, W2, b2, bnA_g, bnA_b, bnG_g, bnG_b,
              sc.R + GNUM * DH);

    predict_k<<<GNUM, 256>>>(sc.R, sc.R + GNUM * DH, Wp1, bp1, Wp2, bp2, (float*)d_out);
}

// round 3
// speedup vs baseline: 1.3937x; 1.3937x over previous
#include <cuda_runtime.h>
#include <cuda_bf16.h>
#include <cstdint>

#define DH 256
#define NMAX 50000
#define EMAX 800000
#define GNUM 64
#define BN_EPS 1e-5f

// ---------------- scratch (static device memory) ----------------
__device__ __align__(16) float g_H [NMAX * DH];
__device__ __align__(16) float g_A [NMAX * DH];
__device__ __align__(16) float g_T1[NMAX * DH];
__device__ __align__(16) float g_T2[NMAX * DH];
__device__ int   g_deg[NMAX + 1];
__device__ int   g_rowptr[NMAX + 1];
__device__ int   g_cursor[NMAX];
__device__ int   g_eidx[EMAX];
__device__ __align__(16) float g_part[256 * 512];
__device__ __align__(16) float g_ac[3 * 512];
__device__ int   g_gstart[GNUM + 1];
__device__ __align__(16) float g_R[2 * GNUM * DH];

// split weights: transposed [N,K] bf16 hi/lo.  emb(256x128) + 4*W1(256x256) + 4*W2(256x256)
#define W_EMB_OFF 0
#define W1_OFF(l) (32768 + (l) * 65536)
#define W2_OFF(l) (32768 + 262144 + (l) * 65536)
#define WTOT      (32768 + 524288)
__device__ __align__(16) __nv_bfloat16 g_Wh[WTOT];
__device__ __align__(16) __nv_bfloat16 g_Wl[WTOT];

// ---------------- helpers ----------------
__device__ __forceinline__ uint32_t smem_u32(const void* p) {
    return (uint32_t)__cvta_generic_to_shared(p);
}
__device__ __forceinline__ void cp16(uint32_t dst, const void* src) {
    asm volatile("cp.async.cg.shared.global [%0], [%1], 16;" :: "r"(dst), "l"(src) : "memory");
}
#define CP_COMMIT() asm volatile("cp.async.commit_group;" ::: "memory")
#define CP_WAIT0()  asm volatile("cp.async.wait_group 0;" ::: "memory")

__device__ __forceinline__ void mma16816(float* d, const uint32_t* a, uint32_t b0, uint32_t b1) {
    asm volatile(
        "mma.sync.aligned.m16n8k16.row.col.f32.bf16.bf16.f32 "
        "{%0,%1,%2,%3}, {%4,%5,%6,%7}, {%8,%9}, {%0,%1,%2,%3};"
        : "+f"(d[0]), "+f"(d[1]), "+f"(d[2]), "+f"(d[3])
        : "r"(a[0]), "r"(a[1]), "r"(a[2]), "r"(a[3]), "r"(b0), "r"(b1));
}

// ---------------- small utility kernels ----------------
__global__ __launch_bounds__(256) void zero_int_k(int* p, int n) {
    int i = blockIdx.x * 256 + threadIdx.x;
    if (i < n) p[i] = 0;
}
__global__ __launch_bounds__(256) void hist_k(const int* __restrict__ dst, int ne, int* deg) {
    int i = blockIdx.x * 256 + threadIdx.x;
    if (i < ne) atomicAdd(&deg[dst[i]], 1);
}
// single-block scan: per-thread serial range + 1024-wide Kogge-Stone
__global__ void scan_fast_k(const int* __restrict__ deg, int* __restrict__ rowptr, int n) {
    __shared__ int ts[1024];
    int t = threadIdx.x;
    int C = (n + 1023) >> 10;
    int b0 = t * C, b1 = min(b0 + C, n);
    int s = 0;
    for (int i = b0; i < b1; i++) s += deg[i];
    ts[t] = s;
    __syncthreads();
    for (int off = 1; off < 1024; off <<= 1) {
        int v = (t >= off) ? ts[t - off] : 0;
        __syncthreads();
        ts[t] += v;
        __syncthreads();
    }
    int run = ts[t] - s;
    for (int i = b0; i < b1; i++) { run += deg[i]; rowptr[i + 1] = run; }
    if (t == 0) rowptr[0] = 0;
}
__global__ __launch_bounds__(256) void copy_int_k(const int* __restrict__ a, int* __restrict__ b, int n) {
    int i = blockIdx.x * 256 + threadIdx.x;
    if (i < n) b[i] = a[i];
}
__global__ __launch_bounds__(256) void fill_k(const int* __restrict__ src, const int* __restrict__ dst,
                                              int ne, int* cursor, int* __restrict__ eidx) {
    int i = blockIdx.x * 256 + threadIdx.x;
    if (i < ne) {
        int p = atomicAdd(&cursor[dst[i]], 1);
        eidx[p] = src[i];
    }
}
__global__ void bounds_k(const int* __restrict__ gid, int n, int* __restrict__ gs) {
    int g = threadIdx.x;
    if (g > GNUM) return;
    int lo = 0, hi = n;
    while (lo < hi) {
        int mid = (lo + hi) >> 1;
        if (gid[mid] < g) lo = mid + 1; else hi = mid;
    }
    gs[g] = lo;
}

// split fp32 weight W[K,N] into transposed bf16 hi/lo pairs [N,K]
__global__ __launch_bounds__(256) void wsplit_k(const float* __restrict__ W,
                                                __nv_bfloat16* __restrict__ Bh,
                                                __nv_bfloat16* __restrict__ Bl, int K, int N) {
    int i = blockIdx.x * 256 + threadIdx.x;
    if (i >= K * N) return;
    int k = i / N, n = i % N;
    float x = W[i];
    __nv_bfloat16 h = __float2bfloat16(x);
    float r = x - __bfloat162float(h);
    Bh[(size_t)n * K + k] = h;
    Bl[(size_t)n * K + k] = __float2bfloat16(r);
}

// ---------------- GIN aggregation ----------------
__global__ void agg_k(const float* __restrict__ H, float* __restrict__ A,
                      const int* __restrict__ rowptr, const int* __restrict__ eidx,
                      const float* __restrict__ eps, int l, int n) {
    int node = blockIdx.x * 8 + threadIdx.y;
    if (node >= n) return;
    int lane = threadIdx.x;
    const float4* h4 = (const float4*)(H + (size_t)node * DH);
    float ep = 1.0f + eps[l];
    float4 a0 = h4[lane];
    float4 a1 = h4[lane + 32];
    a0.x *= ep; a0.y *= ep; a0.z *= ep; a0.w *= ep;
    a1.x *= ep; a1.y *= ep; a1.z *= ep; a1.w *= ep;
    int beg = rowptr[node], end = rowptr[node + 1];
    for (int j = beg; j < end; j++) {
        const float4* s4 = (const float4*)(H + (size_t)eidx[j] * DH);
        float4 b0 = s4[lane];
        float4 b1 = s4[lane + 32];
        a0.x += b0.x; a0.y += b0.y; a0.z += b0.z; a0.w += b0.w;
        a1.x += b1.x; a1.y += b1.y; a1.z += b1.z; a1.w += b1.w;
    }
    float4* o4 = (float4*)(A + (size_t)node * DH);
    o4[lane] = a0;
    o4[lane + 32] = a1;
}

// ---------------- mma.sync GEMM: C[M,256] = op(A)[M,K] @ W[K,256] + bias ----------------
// W pre-transposed [256,K] bf16 hi/lo.  A fp32 split on the fly (split-2, 3 products).
// TRANS=1: A' = relu(tac[k]*A + tac[256+k]) before split (folded BN1+ReLU).
// CTA tile 128x128 (grid.y = 2), 8 warps as 4(M)x2(N), warp tile 32x64.
#define APITCH 72          // bytes per A smem row (32 bf16 + pad)
#define BPITCH 80          // bytes per B smem row (16B aligned for cp.async)
#define OFF_AH   0
#define OFF_AL   9216      // 128*72
#define OFF_B    18432
#define BSTAGE   20480     // 128*80 * 2 (hi+lo)
#define OFF_BIAS (18432 + 2 * BSTAGE)   // 59392
#define SMEM_GEMM (OFF_BIAS + 512)      // 59904

template <int TRANS>
__global__ __launch_bounds__(256, 2) void gemm_mma_k(
    const float* __restrict__ A, const __nv_bfloat16* __restrict__ Bh,
    const __nv_bfloat16* __restrict__ Bl, const float* __restrict__ bias,
    const float* __restrict__ tac, float* __restrict__ C, int M, int K)
{
    extern __shared__ char smem[];
    uint32_t sbase = smem_u32(smem);
    int tid = threadIdx.x;
    int wid = tid >> 5, lane = tid & 31;
    int wm = wid >> 1, wn = wid & 1;
    int g = lane >> 2, tq = lane & 3;
    int m0 = blockIdx.x * 128, n0 = blockIdx.y * 128;
    int NC = K >> 5;

    if (tid < 32) ((float4*)(smem + OFF_BIAS))[tid] = ((const float4*)(bias + n0))[tid];

    // A load geometry: thread -> row tid>>1, 16 consecutive floats at col (tid&1)*16
    int arow = tid >> 1;
    int acol0 = (tid & 1) * 16;
    bool arowok = (m0 + arow) < M;
    const float* aptr = A + (size_t)(m0 + arow) * K + acol0;

    // B cp.async geometry: idx -> row idx>>2, 16B part idx&3
    int br0 = tid >> 2, bp0 = tid & 3;
    int br1 = (tid + 256) >> 2, bp1 = tid & 3;  // +256: row += 64, part same
    const char* bhrow0 = (const char*)(Bh + (size_t)(n0 + br0) * K);
    const char* blrow0 = (const char*)(Bl + (size_t)(n0 + br0) * K);
    const char* bhrow1 = (const char*)(Bh + (size_t)(n0 + br1) * K);
    const char* blrow1 = (const char*)(Bl + (size_t)(n0 + br1) * K);

    float acc[2][8][4];
#pragma unroll
    for (int mt = 0; mt < 2; mt++)
#pragma unroll
        for (int nn = 0; nn < 8; nn++)
#pragma unroll
            for (int r = 0; r < 4; r++) acc[mt][nn][r] = 0.0f;

    float4 pa[4];

    // ---- prologue: chunk 0 ----
    {
        uint32_t bs = sbase + OFF_B;
        cp16(bs + br0 * BPITCH + bp0 * 16, bhrow0 + bp0 * 16);
        cp16(bs + 10240 + br0 * BPITCH + bp0 * 16, blrow0 + bp0 * 16);
        cp16(bs + br1 * BPITCH + bp1 * 16, bhrow1 + bp1 * 16);
        cp16(bs + 10240 + br1 * BPITCH + bp1 * 16, blrow1 + bp1 * 16);
        CP_COMMIT();
#pragma unroll
        for (int q = 0; q < 4; q++)
            pa[q] = arowok ? *(const float4*)(aptr + q * 4) : make_float4(0.f, 0.f, 0.f, 0.f);
    }

    for (int kc = 0; kc < NC; kc++) {
        int s = kc & 1;
        // store A chunk kc (in pa) into smem, split hi/lo
        {
            int kbase = kc * 32;
#pragma unroll
            for (int q = 0; q < 4; q++) {
                float4 v = pa[q];
                if (TRANS) {
                    float4 av = *(const float4*)&tac[kbase + acol0 + q * 4];
                    float4 cv = *(const float4*)&tac[256 + kbase + acol0 + q * 4];
                    v.x = fmaxf(fmaf(av.x, v.x, cv.x), 0.f);
                    v.y = fmaxf(fmaf(av.y, v.y, cv.y), 0.f);
                    v.z = fmaxf(fmaf(av.z, v.z, cv.z), 0.f);
                    v.w = fmaxf(fmaf(av.w, v.w, cv.w), 0.f);
                }
                __nv_bfloat16 hx = __float2bfloat16(v.x);
                __nv_bfloat16 hy = __float2bfloat16(v.y);
                __nv_bfloat16 hz = __float2bfloat16(v.z);
                __nv_bfloat16 hw = __float2bfloat16(v.w);
                __nv_bfloat16 lx = __float2bfloat16(v.x - __bfloat162float(hx));
                __nv_bfloat16 ly = __float2bfloat16(v.y - __bfloat162float(hy));
                __nv_bfloat16 lz = __float2bfloat16(v.z - __bfloat162float(hz));
                __nv_bfloat16 lw = __float2bfloat16(v.w - __bfloat162float(hw));
                __nv_bfloat162 hp0 = __halves2bfloat162(hx, hy);
                __nv_bfloat162 hp1 = __halves2bfloat162(hz, hw);
                __nv_bfloat162 lp0 = __halves2bfloat162(lx, ly);
                __nv_bfloat162 lp1 = __halves2bfloat162(lz, lw);
                uint32_t off = arow * APITCH + (acol0 + q * 4) * 2;
                *(uint2*)(smem + OFF_AH + off) = make_uint2(*(uint32_t*)&hp0, *(uint32_t*)&hp1);
                *(uint2*)(smem + OFF_AL + off) = make_uint2(*(uint32_t*)&lp0, *(uint32_t*)&lp1);
            }
        }
        CP_WAIT0();
        __syncthreads();

        // prefetch chunk kc+1
        bool more = (kc + 1) < NC;
        if (more) {
            int kb = (kc + 1) * 32;
            uint32_t bs = sbase + OFF_B + ((kc + 1) & 1) * BSTAGE;
            int boff = kb * 2;  // bytes into each W row
            cp16(bs + br0 * BPITCH + bp0 * 16, bhrow0 + boff + bp0 * 16);
            cp16(bs + 10240 + br0 * BPITCH + bp0 * 16, blrow0 + boff + bp0 * 16);
            cp16(bs + br1 * BPITCH + bp1 * 16, bhrow1 + boff + bp1 * 16);
            cp16(bs + 10240 + br1 * BPITCH + bp1 * 16, blrow1 + boff + bp1 * 16);
            CP_COMMIT();
#pragma unroll
            for (int q = 0; q < 4; q++)
                pa[q] = arowok ? *(const float4*)(aptr + kb + q * 4) : make_float4(0.f, 0.f, 0.f, 0.f);
        }

        // compute chunk kc
        {
            uint32_t bsoff = OFF_B + s * BSTAGE;
#pragma unroll
            for (int ks = 0; ks < 2; ks++) {
                int kk = ks * 16;
                uint32_t ah[2][4], al[2][4];
#pragma unroll
                for (int mt = 0; mt < 2; mt++) {
                    uint32_t o = (uint32_t)(wm * 32 + mt * 16 + g) * APITCH + (kk + 2 * tq) * 2;
                    ah[mt][0] = *(const uint32_t*)(smem + OFF_AH + o);
                    ah[mt][1] = *(const uint32_t*)(smem + OFF_AH + o + 8 * APITCH);
                    ah[mt][2] = *(const uint32_t*)(smem + OFF_AH + o + 16);
                    ah[mt][3] = *(const uint32_t*)(smem + OFF_AH + o + 8 * APITCH + 16);
                    al[mt][0] = *(const uint32_t*)(smem + OFF_AL + o);
                    al[mt][1] = *(const uint32_t*)(smem + OFF_AL + o + 8 * APITCH);
                    al[mt][2] = *(const uint32_t*)(smem + OFF_AL + o + 16);
                    al[mt][3] = *(const uint32_t*)(smem + OFF_AL + o + 8 * APITCH + 16);
                }
#pragma unroll
                for (int nn = 0; nn < 8; nn++) {
                    uint32_t bo = bsoff + (uint32_t)(wn * 64 + nn * 8 + g) * BPITCH + (kk + 2 * tq) * 2;
                    uint32_t bh0 = *(const uint32_t*)(smem + bo);
                    uint32_t bh1 = *(const uint32_t*)(smem + bo + 16);
                    uint32_t bl0 = *(const uint32_t*)(smem + bo + 10240);
                    uint32_t bl1 = *(const uint32_t*)(smem + bo + 10240 + 16);
                    mma16816(acc[0][nn], ah[0], bh0, bh1);
                    mma16816(acc[1][nn], ah[1], bh0, bh1);
                    mma16816(acc[0][nn], ah[0], bl0, bl1);
                    mma16816(acc[1][nn], ah[1], bl0, bl1);
                    mma16816(acc[0][nn], al[0], bh0, bh1);
                    mma16816(acc[1][nn], al[1], bh0, bh1);
                }
            }
        }
        __syncthreads();
    }

    // epilogue
    const float* biasS = (const float*)(smem + OFF_BIAS);
#pragma unroll
    for (int mt = 0; mt < 2; mt++) {
        int row = m0 + wm * 32 + mt * 16 + g;
#pragma unroll
        for (int nn = 0; nn < 8; nn++) {
            int colr = wn * 64 + nn * 8 + 2 * tq;
            float b0 = biasS[colr], b1 = biasS[colr + 1];
            int col = n0 + colr;
            if (row < M)
                *(float2*)&C[(size_t)row * 256 + col] =
                    make_float2(acc[mt][nn][0] + b0, acc[mt][nn][1] + b1);
            if (row + 8 < M)
                *(float2*)&C[(size_t)(row + 8) * 256 + col] =
                    make_float2(acc[mt][nn][2] + b0, acc[mt][nn][3] + b1);
        }
    }
}

// ---------------- column stats ----------------
template <int TRANS>
__global__ void colstats_k(const float* __restrict__ T, const float* __restrict__ tac,
                           float* __restrict__ part, int M) {
    int c = threadIdx.x;
    int r0 = blockIdx.x * 256;
    int r1 = min(r0 + 256, M);
    float a = 0.f, b = 0.f;
    if (TRANS) { a = tac[c]; b = tac[256 + c]; }
    float s = 0.f, ss = 0.f;
    for (int r = r0; r < r1; r++) {
        float x = T[(size_t)r * DH + c];
        if (TRANS) x = fmaxf(a * x + b, 0.f);
        s += x;
        ss += x * x;
    }
    part[blockIdx.x * 512 + c] = s;
    part[blockIdx.x * 512 + 256 + c] = ss;
}

__global__ void finalize_k(const float* __restrict__ part, int nb, int n,
                           const float* __restrict__ gamma, const float* __restrict__ beta,
                           float* __restrict__ ac) {
    int c = threadIdx.x;
    float s = 0.f, ss = 0.f;
    for (int b = 0; b < nb; b++) {
        s += part[b * 512 + c];
        ss += part[b * 512 + 256 + c];
    }
    float inv = 1.0f / (float)n;
    float m = s * inv;
    float v = ss * inv - m * m;
    float a = gamma[c] * rsqrtf(v + BN_EPS);
    ac[c] = a;
    ac[256 + c] = beta[c] - a * m;
}

__global__ __launch_bounds__(256) void update_k(float* __restrict__ H, const float* __restrict__ T2,
                                                const float* __restrict__ acA, const float* __restrict__ acG,
                                                int n4) {
    int i = blockIdx.x * 256 + threadIdx.x;
    if (i >= n4) return;
    int cb = (i * 4) & 255;
    float4 t  = ((const float4*)T2)[i];
    float4 aA = *(const float4*)&acA[cb];
    float4 cA = *(const float4*)&acA[256 + cb];
    float4 aG = *(const float4*)&acG[cb];
    float4 cG = *(const float4*)&acG[256 + cb];
    float4 h  = ((float4*)H)[i];
    h.x += fmaxf(aG.x * fmaxf(aA.x * t.x + cA.x, 0.f) + cG.x, 0.f);
    h.y += fmaxf(aG.y * fmaxf(aA.y * t.y + cA.y, 0.f) + cG.y, 0.f);
    h.z += fmaxf(aG.z * fmaxf(aA.z * t.z + cA.z, 0.f) + cG.z, 0.f);
    h.w += fmaxf(aG.w * fmaxf(aA.w * t.w + cA.w, 0.f) + cG.w, 0.f);
    ((float4*)H)[i] = h;
}

__global__ void readout_k(const float* __restrict__ H, const int* __restrict__ gs,
                          float* __restrict__ R) {
    int g = blockIdx.x;
    int c = threadIdx.x;
    int beg = gs[g], end = gs[g + 1];
    float s = 0.f;
    for (int i = beg; i < end; i++) s += H[(size_t)i * DH + c];
    R[g * DH + c] = s;
}

__global__ void predict_k(const float* __restrict__ Rg, const float* __restrict__ Rq,
                          const float* __restrict__ Wp1, const float* __restrict__ bp1,
                          const float* __restrict__ Wp2, const float* __restrict__ bp2,
                          float* __restrict__ out) {
    int g = blockIdx.x;
    int t = threadIdx.x;
    __shared__ float d[256];
    __shared__ float red[256];
    d[t] = fabsf(Rg[g * DH + t] - Rq[g * DH + t]);
    __syncthreads();
    float acc = bp1[t];
    for (int k = 0; k < 256; k++) acc += d[k] * Wp1[k * 256 + t];
    acc = fmaxf(acc, 0.f);
    red[t] = acc * Wp2[t];
    __syncthreads();
    for (int s = 128; s > 0; s >>= 1) {
        if (t < s) red[t] += red[t + s];
        __syncthreads();
    }
    if (t == 0) out[g] = red[0] + bp2[0];
}

// ---------------- host orchestration ----------------
struct Scratch {
    float *H, *A, *T1, *T2, *part, *ac, *R;
    int *deg, *rowptr, *cursor, *eidx, *gstart;
    __nv_bfloat16 *Wh, *Wl;
};

static void get_scratch(Scratch& s) {
    cudaGetSymbolAddress((void**)&s.H, g_H);
    cudaGetSymbolAddress((void**)&s.A, g_A);
    cudaGetSymbolAddress((void**)&s.T1, g_T1);
    cudaGetSymbolAddress((void**)&s.T2, g_T2);
    cudaGetSymbolAddress((void**)&s.part, g_part);
    cudaGetSymbolAddress((void**)&s.ac, g_ac);
    cudaGetSymbolAddress((void**)&s.R, g_R);
    cudaGetSymbolAddress((void**)&s.deg, g_deg);
    cudaGetSymbolAddress((void**)&s.rowptr, g_rowptr);
    cudaGetSymbolAddress((void**)&s.cursor, g_cursor);
    cudaGetSymbolAddress((void**)&s.eidx, g_eidx);
    cudaGetSymbolAddress((void**)&s.gstart, g_gstart);
    cudaGetSymbolAddress((void**)&s.Wh, g_Wh);
    cudaGetSymbolAddress((void**)&s.Wl, g_Wl);
}

static void run_graph(const Scratch& sc, const float* X, int n,
                      const int* src, const int* dst, int ne, const int* gid,
                      const float* b_emb, const float* eps,
                      const float* b1, const float* bn1_g, const float* bn1_b,
                      const float* b2, const float* bnA_g, const float* bnA_b,
                      const float* bnG_g, const float* bnG_b,
                      float* R) {
    dim3 gg((n + 127) / 128, 2);
    int sb = (n + 255) / 256;

    // node embedding: H = X @ W_emb + b_emb  (K=128)
    gemm_mma_k<0><<<gg, 256, SMEM_GEMM>>>(X, sc.Wh + W_EMB_OFF, sc.Wl + W_EMB_OFF,
                                          b_emb, nullptr, sc.H, n, 128);

    // CSR by destination
    zero_int_k<<<(n + 256) / 256, 256>>>(sc.deg, n + 1);
    hist_k<<<(ne + 255) / 256, 256>>>(dst, ne, sc.deg);
    scan_fast_k<<<1, 1024>>>(sc.deg, sc.rowptr, n);
    copy_int_k<<<(n + 255) / 256, 256>>>(sc.rowptr, sc.cursor, n);
    fill_k<<<(ne + 255) / 256, 256>>>(src, dst, ne, sc.cursor, sc.eidx);
    bounds_k<<<1, GNUM + 1>>>(gid, n, sc.gstart);

    for (int l = 0; l < 4; l++) {
        int bo = l * 256;
        agg_k<<<(n + 7) / 8, dim3(32, 8)>>>(sc.H, sc.A, sc.rowptr, sc.eidx, eps, l, n);
        // T1 = A @ W1 + b1
        gemm_mma_k<0><<<gg, 256, SMEM_GEMM>>>(sc.A, sc.Wh + W1_OFF(l), sc.Wl + W1_OFF(l),
                                              b1 + bo, nullptr, sc.T1, n, 256);
        colstats_k<0><<<sb, 256>>>(sc.T1, nullptr, sc.part, n);
        finalize_k<<<1, 256>>>(sc.part, sb, n, bn1_g + bo, bn1_b + bo, sc.ac);
        // T2 = relu(bn1(T1)) @ W2 + b2  (bn1+relu folded into A-split)
        gemm_mma_k<1><<<gg, 256, SMEM_GEMM>>>(sc.T1, sc.Wh + W2_OFF(l), sc.Wl + W2_OFF(l),
                                              b2 + bo, sc.ac, sc.T2, n, 256);
        colstats_k<0><<<sb, 256>>>(sc.T2, nullptr, sc.part, n);
        finalize_k<<<1, 256>>>(sc.part, sb, n, bnA_g + bo, bnA_b + bo, sc.ac + 512);
        colstats_k<1><<<sb, 256>>>(sc.T2, sc.ac + 512, sc.part, n);
        finalize_k<<<1, 256>>>(sc.part, sb, n, bnG_g + bo, bnG_b + bo, sc.ac + 1024);
        update_k<<<((n * 64) + 255) / 256, 256>>>(sc.H, sc.T2, sc.ac + 512, sc.ac + 1024, n * 64);
    }
    readout_k<<<GNUM, 256>>>(sc.H, sc.gstart, R);
}

extern "C" void kernel_launch(void* const* d_in, const int* in_sizes, int n_in,
                              void* d_out, int out_size) {
    const float* X     = (const float*)d_in[0];
    const float* X_q   = (const float*)d_in[2];
    const float* W_emb = (const float*)d_in[4];
    const float* b_emb = (const float*)d_in[5];
    const float* eps   = (const float*)d_in[6];
    const float* W1    = (const float*)d_in[7];
    const float* b1    = (const float*)d_in[8];
    const float* bn1_g = (const float*)d_in[9];
    const float* bn1_b = (const float*)d_in[10];
    const float* W2    = (const float*)d_in[11];
    const float* b2    = (const float*)d_in[12];
    const float* bnA_g = (const float*)d_in[13];
    const float* bnA_b = (const float*)d_in[14];
    const float* bnG_g = (const float*)d_in[15];
    const float* bnG_b = (const float*)d_in[16];
    const float* Wp1   = (const float*)d_in[17];
    const float* bp1   = (const float*)d_in[18];
    const float* Wp2   = (const float*)d_in[19];
    const float* bp2   = (const float*)d_in[20];
    const int* src_g   = (const int*)d_in[21];
    const int* dst_g   = (const int*)d_in[22];
    const int* gid_g   = (const int*)d_in[23];
    const int* src_q   = (const int*)d_in[24];
    const int* dst_q   = (const int*)d_in[25];
    const int* gid_q   = (const int*)d_in[26];

    int n_g = in_sizes[0] / 128;
    int e_g = in_sizes[21];
    int n_q = in_sizes[2] / 128;
    int e_q = in_sizes[24];

    Scratch sc;
    get_scratch(sc);

    cudaFuncSetAttribute(gemm_mma_k<0>, cudaFuncAttributeMaxDynamicSharedMemorySize, SMEM_GEMM);
    cudaFuncSetAttribute(gemm_mma_k<1>, cudaFuncAttributeMaxDynamicSharedMemorySize, SMEM_GEMM);

    // pre-split weights into transposed bf16 hi/lo
    wsplit_k<<<(128 * 256 + 255) / 256, 256>>>(W_emb, sc.Wh + W_EMB_OFF, sc.Wl + W_EMB_OFF, 128, 256);
    for (int l = 0; l < 4; l++) {
        wsplit_k<<<(256 * 256 + 255) / 256, 256>>>(W1 + (size_t)l * 65536,
                                                   sc.Wh + W1_OFF(l), sc.Wl + W1_OFF(l), 256, 256);
        wsplit_k<<<(256 * 256 + 255) / 256, 256>>>(W2 + (size_t)l * 65536,
                                                   sc.Wh + W2_OFF(l), sc.Wl + W2_OFF(l), 256, 256);
    }

    run_graph(sc, X, n_g, src_g, dst_g, e_g, gid_g, b_emb, eps,
              b1, bn1_g, bn1_b, b2, bnA_g, bnA_b, bnG_g, bnG_b, sc.R);
    run_graph(sc, X_q, n_q, src_q, dst_q, e_q, gid_q, b_emb, eps,
              b1, bn1_g, bn1_b, b2, bnA_g, bnA_b, bnG_g, bnG_b, sc.R + GNUM * DH);

    predict_k<<<GNUM, 256>>>(sc.R, sc.R + GNUM * DH, Wp1, bp1, Wp2, bp2, (float*)d_out);
}